// round 15
// baseline (speedup 1.0000x reference)
#include <cuda_runtime.h>
#include <cuda_fp16.h>
#include <cuda_fp8.h>
#include <cstdint>

#define N_NODES 100000
#define N_EDGES 1600000
#define FNODE   32
#define FGLOB   16
#define HDIM    64
#define OUTDIM  64
#define MAXDEG  128    // Poisson(16) max over 100k nodes ~50; 128 is a >=8-sigma bound

#define MSG_SCALE     64.0f
#define INV_MSG_SCALE (1.0f / 64.0f)

// ---------------- scratch (device globals: no allocations allowed) ----------
__device__ int   g_cnt[N_NODES];                                 // degree; fill cursor
__device__ __align__(16) int g_csr[(size_t)N_NODES * MAXDEG];    // slot-based CSR
__device__ float g_dis[N_NODES];
__device__ __align__(16) __half g_wh[3][HDIM * HDIM];            // [0]=Wc(32x64), [1],[2]=fp16 W
__device__ float g_bc[HDIM];                                     // bc = bn @ W0
__device__ __align__(16) __half g_hf[(size_t)N_NODES * HDIM];    // node features fp16
__device__ __align__(16) unsigned int g_hw8[(size_t)N_NODES * 16]; // fp8x4 msgs, 64B/row
__device__ float g_pool[HDIM];

// ---------------- prep: Wc = Wn@W0, bc = bn@W0 (block 0); W1,W2 -> fp16 ----------
__global__ void k_prep(const float* __restrict__ w0, const float* __restrict__ w1,
                       const float* __restrict__ w2, const float* __restrict__ wn,
                       const float* __restrict__ bn) {
    if (blockIdx.x == 0) {
        __shared__ float WnS[FNODE * HDIM];
        __shared__ float W0S[HDIM * HDIM];
        int tid = threadIdx.x;
        for (int i = tid; i < FNODE * HDIM / 4; i += 256)
            reinterpret_cast<float4*>(WnS)[i] = reinterpret_cast<const float4*>(wn)[i];
        for (int i = tid; i < HDIM * HDIM / 4; i += 256)
            reinterpret_cast<float4*>(W0S)[i] = reinterpret_cast<const float4*>(w0)[i];
        __syncthreads();
        for (int idx = tid; idx < FNODE * HDIM; idx += 256) {
            int i = idx >> 6, j = idx & 63;
            float s = 0.f;
            #pragma unroll 8
            for (int k = 0; k < HDIM; k++) s += WnS[i * HDIM + k] * W0S[k * HDIM + j];
            g_wh[0][idx] = __float2half(s);
        }
        if (tid < HDIM) {
            float s = 0.f;
            #pragma unroll 8
            for (int k = 0; k < HDIM; k++) s += bn[k] * W0S[k * HDIM + tid];
            g_bc[tid] = s;
        }
    } else {
        int base = (blockIdx.x - 1) * blockDim.x + threadIdx.x;
        int stride = (gridDim.x - 1) * blockDim.x;
        for (int idx = base; idx < 2 * HDIM * HDIM; idx += stride) {
            if (idx < HDIM * HDIM) g_wh[1][idx] = __float2half(w1[idx]);
            else                   g_wh[2][idx - HDIM * HDIM] = __float2half(w2[idx - HDIM * HDIM]);
        }
    }
}

// ---------------- fused count+fill: slot-based CSR (one atomic per edge) ---------
__global__ void k_fill(const int* __restrict__ src, const int* __restrict__ dst) {
    int e = blockIdx.x * blockDim.x + threadIdx.x;
    if (e < N_EDGES) {
        int d = dst[e];
        int slot = atomicAdd(&g_cnt[d], 1);
        g_csr[(size_t)d * MAXDEG + slot] = src[e];
    }
}

// ---------------- dis = rsqrt(cnt+1) + pool zero ----------------------------------
__global__ void k_dis() {
    int i = blockIdx.x * blockDim.x + threadIdx.x;
    if (i < N_NODES) g_dis[i] = rsqrtf((float)(g_cnt[i] + 1));
    if (i < HDIM) g_pool[i] = 0.f;
}

// ---------------- fp8x2 -> half2 helpers -----------------------------------------
__device__ __forceinline__ __half2 fp8x2_to_h2(unsigned short u) {
    __half2_raw hr = __nv_cvt_fp8x2_to_halfraw2(u, __NV_E4M3);
    return *reinterpret_cast<__half2*>(&hr);
}
__device__ __forceinline__ __half2 u2h2(unsigned int u) {
    return *reinterpret_cast<__half2*>(&u);
}

#define APITCH 72      // halves; conflict-free ldmatrix (144B rows)
#define S8P    36      // ushorts per padded fp8 row (32 data + 4 pad)

// ---------------- layer-1 HMMA: msgs = fp8(64 * (x @ Wc + bc)), K=32 --------------
// UNSCALED by dis (applied per-edge in agg) -> no dependence on the graph build.
__global__ void k_hmma1(const float* __restrict__ xin, unsigned int* __restrict__ out8) {
    __shared__ __half Wsm[FNODE * APITCH];    // Wc: 32 K-rows x 64 cols
    __shared__ __half Asm[128 * APITCH];
    __shared__ float BcS[HDIM];
    int tid = threadIdx.x;
    int lane = tid & 31, wid = tid >> 5;
    int rowBase = blockIdx.x * 128;

    for (int i = tid; i < FNODE * 8; i += 256) {
        int r = i >> 3, c8 = i & 7;
        *reinterpret_cast<uint4*>(&Wsm[r * APITCH + c8 * 8]) =
            *reinterpret_cast<const uint4*>(&g_wh[0][r * HDIM + c8 * 8]);
    }
    if (tid < HDIM) BcS[tid] = g_bc[tid];

    for (int i = tid; i < 128 * 4; i += 256) {
        int r = i >> 2, c8 = i & 3;
        int gr = rowBase + r;
        uint4 hv = make_uint4(0u, 0u, 0u, 0u);
        if (gr < N_NODES) {
            const float4* xr = reinterpret_cast<const float4*>(xin + (size_t)gr * FNODE + c8 * 8);
            float4 a = __ldg(&xr[0]);
            float4 b = __ldg(&xr[1]);
            __half2 h0 = __floats2half2_rn(a.x, a.y);
            __half2 h1 = __floats2half2_rn(a.z, a.w);
            __half2 h2 = __floats2half2_rn(b.x, b.y);
            __half2 h3 = __floats2half2_rn(b.z, b.w);
            hv.x = *reinterpret_cast<unsigned*>(&h0);
            hv.y = *reinterpret_cast<unsigned*>(&h1);
            hv.z = *reinterpret_cast<unsigned*>(&h2);
            hv.w = *reinterpret_cast<unsigned*>(&h3);
        }
        *reinterpret_cast<uint4*>(&Asm[r * APITCH + c8 * 8]) = hv;
    }
    __syncthreads();

    float acc[8][4];
    #pragma unroll
    for (int j = 0; j < 8; j++)
        #pragma unroll
        for (int q = 0; q < 4; q++) acc[j][q] = 0.f;

    uint32_t aAddr = (uint32_t)__cvta_generic_to_shared(
        &Asm[(wid * 16 + (lane & 15)) * APITCH + (lane >> 4) * 8]);
    uint32_t bAddr = (uint32_t)__cvta_generic_to_shared(
        &Wsm[(lane & 15) * APITCH]);

    #pragma unroll
    for (int k = 0; k < 2; k++) {             // K=32 -> 2 k-steps
        uint32_t a0, a1, a2, a3;
        asm volatile("ldmatrix.sync.aligned.m8n8.x4.shared.b16 {%0,%1,%2,%3}, [%4];\n"
                     : "=r"(a0), "=r"(a1), "=r"(a2), "=r"(a3)
                     : "r"(aAddr + k * 16 * 2));
        #pragma unroll
        for (int j = 0; j < 8; j++) {
            uint32_t b0, b1;
            asm volatile("ldmatrix.sync.aligned.m8n8.x2.trans.shared.b16 {%0,%1}, [%2];\n"
                         : "=r"(b0), "=r"(b1)
                         : "r"(bAddr + (k * 16 * APITCH + j * 8) * 2));
            asm volatile("mma.sync.aligned.m16n8k16.row.col.f32.f16.f16.f32 "
                         "{%0,%1,%2,%3}, {%4,%5,%6,%7}, {%8,%9}, {%0,%1,%2,%3};\n"
                         : "+f"(acc[j][0]), "+f"(acc[j][1]), "+f"(acc[j][2]), "+f"(acc[j][3])
                         : "r"(a0), "r"(a1), "r"(a2), "r"(a3), "r"(b0), "r"(b1));
        }
    }

    __syncthreads();
    unsigned short* S8 = reinterpret_cast<unsigned short*>(Asm);   // [128][S8P]

    int g = lane >> 2, q = lane & 3;
    int r0l = wid * 16 + g;
    int r1l = r0l + 8;
    #pragma unroll
    for (int j = 0; j < 8; j++) {
        float bcx = BcS[j * 8 + q * 2];
        float bcy = BcS[j * 8 + q * 2 + 1];
        S8[r0l * S8P + j * 4 + q] = __nv_cvt_float2_to_fp8x2(
            make_float2((acc[j][0] + bcx) * MSG_SCALE, (acc[j][1] + bcy) * MSG_SCALE),
            __NV_SATFINITE, __NV_E4M3);
        S8[r1l * S8P + j * 4 + q] = __nv_cvt_float2_to_fp8x2(
            make_float2((acc[j][2] + bcx) * MSG_SCALE, (acc[j][3] + bcy) * MSG_SCALE),
            __NV_SATFINITE, __NV_E4M3);
    }
    __syncthreads();

    for (int i = tid; i < 128 * 8; i += 256) {
        int r = i >> 3, c = i & 7;
        int grow = rowBase + r;
        if (grow < N_NODES) {
            uint2 v = *reinterpret_cast<const uint2*>(&S8[r * S8P + c * 4]);
            *reinterpret_cast<uint2*>(&out8[(size_t)grow * 16 + c * 2]) = v;
        }
    }
}

// ---------------- HMMA conv transform (layers 2,3): pre-scaled msgs ---------------
__global__ void k_hmma(const __half* __restrict__ hin, const __half* __restrict__ wh,
                       unsigned int* __restrict__ out8) {
    __shared__ __half Wsm[HDIM * APITCH];
    __shared__ __half Asm[128 * APITCH];
    int tid = threadIdx.x;
    int lane = tid & 31, wid = tid >> 5;
    int rowBase = blockIdx.x * 128;

    for (int i = tid; i < HDIM * 8; i += 256) {
        int r = i >> 3, c8 = i & 7;
        *reinterpret_cast<uint4*>(&Wsm[r * APITCH + c8 * 8]) =
            *reinterpret_cast<const uint4*>(wh + r * HDIM + c8 * 8);
    }
    for (int i = tid; i < 128 * 8; i += 256) {
        int r = i >> 3, c8 = i & 7;
        int gr = rowBase + r;
        uint4 v = make_uint4(0u, 0u, 0u, 0u);
        if (gr < N_NODES)
            v = *reinterpret_cast<const uint4*>(hin + (size_t)gr * HDIM + c8 * 8);
        *reinterpret_cast<uint4*>(&Asm[r * APITCH + c8 * 8]) = v;
    }
    __syncthreads();

    float acc[8][4];
    #pragma unroll
    for (int j = 0; j < 8; j++)
        #pragma unroll
        for (int q = 0; q < 4; q++) acc[j][q] = 0.f;

    uint32_t aAddr = (uint32_t)__cvta_generic_to_shared(
        &Asm[(wid * 16 + (lane & 15)) * APITCH + (lane >> 4) * 8]);
    uint32_t bAddr = (uint32_t)__cvta_generic_to_shared(
        &Wsm[(lane & 15) * APITCH]);

    #pragma unroll
    for (int k = 0; k < 4; k++) {
        uint32_t a0, a1, a2, a3;
        asm volatile("ldmatrix.sync.aligned.m8n8.x4.shared.b16 {%0,%1,%2,%3}, [%4];\n"
                     : "=r"(a0), "=r"(a1), "=r"(a2), "=r"(a3)
                     : "r"(aAddr + k * 16 * 2));
        #pragma unroll
        for (int j = 0; j < 8; j++) {
            uint32_t b0, b1;
            asm volatile("ldmatrix.sync.aligned.m8n8.x2.trans.shared.b16 {%0,%1}, [%2];\n"
                         : "=r"(b0), "=r"(b1)
                         : "r"(bAddr + (k * 16 * APITCH + j * 8) * 2));
            asm volatile("mma.sync.aligned.m16n8k16.row.col.f32.f16.f16.f32 "
                         "{%0,%1,%2,%3}, {%4,%5,%6,%7}, {%8,%9}, {%0,%1,%2,%3};\n"
                         : "+f"(acc[j][0]), "+f"(acc[j][1]), "+f"(acc[j][2]), "+f"(acc[j][3])
                         : "r"(a0), "r"(a1), "r"(a2), "r"(a3), "r"(b0), "r"(b1));
        }
    }

    __syncthreads();
    unsigned short* S8 = reinterpret_cast<unsigned short*>(Asm);   // [128][S8P]

    int g = lane >> 2, q = lane & 3;
    int r0l = wid * 16 + g;
    int r1l = r0l + 8;
    int gr0 = rowBase + r0l, gr1 = rowBase + r1l;
    float d0 = (gr0 < N_NODES) ? g_dis[gr0] * MSG_SCALE : 0.f;
    float d1 = (gr1 < N_NODES) ? g_dis[gr1] * MSG_SCALE : 0.f;
    #pragma unroll
    for (int j = 0; j < 8; j++) {
        S8[r0l * S8P + j * 4 + q] = __nv_cvt_float2_to_fp8x2(
            make_float2(acc[j][0] * d0, acc[j][1] * d0), __NV_SATFINITE, __NV_E4M3);
        S8[r1l * S8P + j * 4 + q] = __nv_cvt_float2_to_fp8x2(
            make_float2(acc[j][2] * d1, acc[j][3] * d1), __NV_SATFINITE, __NV_E4M3);
    }
    __syncthreads();

    for (int i = tid; i < 128 * 8; i += 256) {
        int r = i >> 3, c = i & 7;
        int grow = rowBase + r;
        if (grow < N_NODES) {
            uint2 v = *reinterpret_cast<const uint2*>(&S8[r * S8P + c * 4]);
            *reinterpret_cast<uint2*>(&out8[(size_t)grow * 16 + c * 2]) = v;
        }
    }
}

// ---------------- aggregation: warp/node, 4 lanes/row, 8 edges per LDG -----------
// EDIS=true : msgs unscaled -> per-edge dis[src] applied via hfma2 (layer 1)
// EDIS=false: msgs pre-scaled by dis[src] (layers 2,3)
template<bool EDIS>
__global__ void k_agg(const uint4* __restrict__ hw,
                      const float* __restrict__ bias, __half* __restrict__ outh) {
    int gw = (blockIdx.x * blockDim.x + threadIdx.x) >> 5;
    int lane = threadIdx.x & 31;
    if (gw >= N_NODES) return;
    int e = lane >> 2;           // edge slot 0..7
    int s = lane & 3;            // uint4 column (16 fp8 cols)

    float disg = __ldg(&g_dis[gw]);

    __half2 a0 = __float2half2_rn(0.f), a1 = a0, a2 = a0, a3 = a0;
    __half2 a4 = a0, a5 = a0, a6 = a0, a7 = a0;

    if (e == 0) {                // self loop
        uint4 v = __ldg(&hw[(size_t)gw * 4 + s]);
        __half2 v0 = fp8x2_to_h2((unsigned short)(v.x & 0xffffu));
        __half2 v1 = fp8x2_to_h2((unsigned short)(v.x >> 16));
        __half2 v2 = fp8x2_to_h2((unsigned short)(v.y & 0xffffu));
        __half2 v3 = fp8x2_to_h2((unsigned short)(v.y >> 16));
        __half2 v4 = fp8x2_to_h2((unsigned short)(v.z & 0xffffu));
        __half2 v5 = fp8x2_to_h2((unsigned short)(v.z >> 16));
        __half2 v6 = fp8x2_to_h2((unsigned short)(v.w & 0xffffu));
        __half2 v7 = fp8x2_to_h2((unsigned short)(v.w >> 16));
        if (EDIS) {
            __half2 dh = __float2half2_rn(disg);
            a0 = __hmul2(v0, dh); a1 = __hmul2(v1, dh);
            a2 = __hmul2(v2, dh); a3 = __hmul2(v3, dh);
            a4 = __hmul2(v4, dh); a5 = __hmul2(v5, dh);
            a6 = __hmul2(v6, dh); a7 = __hmul2(v7, dh);
        } else {
            a0 = v0; a1 = v1; a2 = v2; a3 = v3;
            a4 = v4; a5 = v5; a6 = v6; a7 = v7;
        }
    }

    int cnt = g_cnt[gw];
    const int* row = g_csr + (size_t)gw * MAXDEG;
    int j = 0;
    for (; j + 8 <= cnt; j += 8) {
        int idx = __ldg(&row[j + e]);
        uint4 v = __ldg(&hw[(size_t)idx * 4 + s]);
        __half2 v0 = fp8x2_to_h2((unsigned short)(v.x & 0xffffu));
        __half2 v1 = fp8x2_to_h2((unsigned short)(v.x >> 16));
        __half2 v2 = fp8x2_to_h2((unsigned short)(v.y & 0xffffu));
        __half2 v3 = fp8x2_to_h2((unsigned short)(v.y >> 16));
        __half2 v4 = fp8x2_to_h2((unsigned short)(v.z & 0xffffu));
        __half2 v5 = fp8x2_to_h2((unsigned short)(v.z >> 16));
        __half2 v6 = fp8x2_to_h2((unsigned short)(v.w & 0xffffu));
        __half2 v7 = fp8x2_to_h2((unsigned short)(v.w >> 16));
        if (EDIS) {
            __half2 dh = __float2half2_rn(__ldg(&g_dis[idx]));
            a0 = __hfma2(v0, dh, a0); a1 = __hfma2(v1, dh, a1);
            a2 = __hfma2(v2, dh, a2); a3 = __hfma2(v3, dh, a3);
            a4 = __hfma2(v4, dh, a4); a5 = __hfma2(v5, dh, a5);
            a6 = __hfma2(v6, dh, a6); a7 = __hfma2(v7, dh, a7);
        } else {
            a0 = __hadd2(a0, v0); a1 = __hadd2(a1, v1);
            a2 = __hadd2(a2, v2); a3 = __hadd2(a3, v3);
            a4 = __hadd2(a4, v4); a5 = __hadd2(a5, v5);
            a6 = __hadd2(a6, v6); a7 = __hadd2(a7, v7);
        }
    }
    int rem = cnt - j;           // 0..7, warp-uniform
    if (e < rem) {
        int idx = __ldg(&row[j + e]);
        uint4 v = __ldg(&hw[(size_t)idx * 4 + s]);
        __half2 v0 = fp8x2_to_h2((unsigned short)(v.x & 0xffffu));
        __half2 v1 = fp8x2_to_h2((unsigned short)(v.x >> 16));
        __half2 v2 = fp8x2_to_h2((unsigned short)(v.y & 0xffffu));
        __half2 v3 = fp8x2_to_h2((unsigned short)(v.y >> 16));
        __half2 v4 = fp8x2_to_h2((unsigned short)(v.z & 0xffffu));
        __half2 v5 = fp8x2_to_h2((unsigned short)(v.z >> 16));
        __half2 v6 = fp8x2_to_h2((unsigned short)(v.w & 0xffffu));
        __half2 v7 = fp8x2_to_h2((unsigned short)(v.w >> 16));
        if (EDIS) {
            __half2 dh = __float2half2_rn(__ldg(&g_dis[idx]));
            a0 = __hfma2(v0, dh, a0); a1 = __hfma2(v1, dh, a1);
            a2 = __hfma2(v2, dh, a2); a3 = __hfma2(v3, dh, a3);
            a4 = __hfma2(v4, dh, a4); a5 = __hfma2(v5, dh, a5);
            a6 = __hfma2(v6, dh, a6); a7 = __hfma2(v7, dh, a7);
        } else {
            a0 = __hadd2(a0, v0); a1 = __hadd2(a1, v1);
            a2 = __hadd2(a2, v2); a3 = __hadd2(a3, v3);
            a4 = __hadd2(a4, v4); a5 = __hadd2(a5, v5);
            a6 = __hadd2(a6, v6); a7 = __hadd2(a7, v7);
        }
    }

    // reduce across edge slots: xor 4, 8, 16 (lane^k keeps s, changes e)
    #pragma unroll
    for (int off = 4; off <= 16; off <<= 1) {
        unsigned u0 = *reinterpret_cast<unsigned*>(&a0);
        unsigned u1 = *reinterpret_cast<unsigned*>(&a1);
        unsigned u2 = *reinterpret_cast<unsigned*>(&a2);
        unsigned u3 = *reinterpret_cast<unsigned*>(&a3);
        unsigned u4 = *reinterpret_cast<unsigned*>(&a4);
        unsigned u5 = *reinterpret_cast<unsigned*>(&a5);
        unsigned u6 = *reinterpret_cast<unsigned*>(&a6);
        unsigned u7 = *reinterpret_cast<unsigned*>(&a7);
        a0 = __hadd2(u2h2(u0), u2h2(__shfl_xor_sync(0xffffffffu, u0, off)));
        a1 = __hadd2(u2h2(u1), u2h2(__shfl_xor_sync(0xffffffffu, u1, off)));
        a2 = __hadd2(u2h2(u2), u2h2(__shfl_xor_sync(0xffffffffu, u2, off)));
        a3 = __hadd2(u2h2(u3), u2h2(__shfl_xor_sync(0xffffffffu, u3, off)));
        a4 = __hadd2(u2h2(u4), u2h2(__shfl_xor_sync(0xffffffffu, u4, off)));
        a5 = __hadd2(u2h2(u5), u2h2(__shfl_xor_sync(0xffffffffu, u5, off)));
        a6 = __hadd2(u2h2(u6), u2h2(__shfl_xor_sync(0xffffffffu, u6, off)));
        a7 = __hadd2(u2h2(u7), u2h2(__shfl_xor_sync(0xffffffffu, u7, off)));
    }

    if (e == 0) {
        float di = disg * INV_MSG_SCALE;
        const float4* b4 = reinterpret_cast<const float4*>(bias) + s * 4;
        float4 bA = __ldg(&b4[0]);
        float4 bB = __ldg(&b4[1]);
        float4 bC = __ldg(&b4[2]);
        float4 bD = __ldg(&b4[3]);
        float2 f0 = __half22float2(a0), f1 = __half22float2(a1);
        float2 f2 = __half22float2(a2), f3 = __half22float2(a3);
        float2 f4 = __half22float2(a4), f5 = __half22float2(a5);
        float2 f6 = __half22float2(a6), f7 = __half22float2(a7);
        __half2 h0 = __floats2half2_rn(fmaxf(fmaf(di, f0.x, bA.x), 0.f),
                                       fmaxf(fmaf(di, f0.y, bA.y), 0.f));
        __half2 h1 = __floats2half2_rn(fmaxf(fmaf(di, f1.x, bA.z), 0.f),
                                       fmaxf(fmaf(di, f1.y, bA.w), 0.f));
        __half2 h2 = __floats2half2_rn(fmaxf(fmaf(di, f2.x, bB.x), 0.f),
                                       fmaxf(fmaf(di, f2.y, bB.y), 0.f));
        __half2 h3 = __floats2half2_rn(fmaxf(fmaf(di, f3.x, bB.z), 0.f),
                                       fmaxf(fmaf(di, f3.y, bB.w), 0.f));
        __half2 h4 = __floats2half2_rn(fmaxf(fmaf(di, f4.x, bC.x), 0.f),
                                       fmaxf(fmaf(di, f4.y, bC.y), 0.f));
        __half2 h5 = __floats2half2_rn(fmaxf(fmaf(di, f5.x, bC.z), 0.f),
                                       fmaxf(fmaf(di, f5.y, bC.w), 0.f));
        __half2 h6 = __floats2half2_rn(fmaxf(fmaf(di, f6.x, bD.x), 0.f),
                                       fmaxf(fmaf(di, f6.y, bD.y), 0.f));
        __half2 h7 = __floats2half2_rn(fmaxf(fmaf(di, f7.x, bD.z), 0.f),
                                       fmaxf(fmaf(di, f7.y, bD.w), 0.f));
        uint4 stA, stB;
        stA.x = *reinterpret_cast<unsigned*>(&h0);
        stA.y = *reinterpret_cast<unsigned*>(&h1);
        stA.z = *reinterpret_cast<unsigned*>(&h2);
        stA.w = *reinterpret_cast<unsigned*>(&h3);
        stB.x = *reinterpret_cast<unsigned*>(&h4);
        stB.y = *reinterpret_cast<unsigned*>(&h5);
        stB.z = *reinterpret_cast<unsigned*>(&h6);
        stB.w = *reinterpret_cast<unsigned*>(&h7);
        uint4* op = reinterpret_cast<uint4*>(outh + (size_t)gw * HDIM + s * 16);
        op[0] = stA;
        op[1] = stB;
    }
}

// ---------------- mean pool over nodes (fp16 input) ------------------------------
__global__ void k_pool(const __half2* __restrict__ h2) {
    __shared__ float2 sh[256];
    int c = threadIdx.x & 31;       // half2 column
    int seg = threadIdx.x >> 5;     // 0..7
    float2 acc = make_float2(0.f, 0.f);
    for (int r = blockIdx.x * 8 + seg; r < N_NODES; r += gridDim.x * 8) {
        float2 v = __half22float2(h2[(size_t)r * 32 + c]);
        acc.x += v.x; acc.y += v.y;
    }
    sh[threadIdx.x] = acc;
    __syncthreads();
    if (threadIdx.x < 32) {
        float2 s = sh[c];
        #pragma unroll
        for (int k = 1; k < 8; k++) {
            s.x += sh[k * 32 + c].x;
            s.y += sh[k * 32 + c].y;
        }
        atomicAdd(&g_pool[2 * c],     s.x);
        atomicAdd(&g_pool[2 * c + 1], s.y);
    }
}

// ---------------- head ------------------------------------------------------------
__global__ void k_head(const float* __restrict__ gf,
                       const float* __restrict__ w_glob, const float* __restrict__ b_glob,
                       const float* __restrict__ w_fc1, const float* __restrict__ b_fc1,
                       const float* __restrict__ w_fc2, const float* __restrict__ b_fc2,
                       float* __restrict__ out) {
    __shared__ float xc[2 * HDIM];
    __shared__ float t1[HDIM];
    int t = threadIdx.x;

    xc[t] = g_pool[t] * (1.0f / (float)N_NODES);

    float a = b_glob[t];
    #pragma unroll
    for (int k = 0; k < FGLOB; k++) a += gf[k] * w_glob[k * HDIM + t];
    xc[HDIM + t] = fmaxf(a, 0.f);
    __syncthreads();

    float u = b_fc1[t];
    #pragma unroll 8
    for (int k = 0; k < 2 * HDIM; k++) u += xc[k] * w_fc1[k * HDIM + t];
    t1[t] = fmaxf(u, 0.f);
    __syncthreads();

    float o = b_fc2[t];
    #pragma unroll 8
    for (int k = 0; k < HDIM; k++) o += t1[k] * w_fc2[k * OUTDIM + t];
    out[t] = o;
}

// ---------------- launch ------------------------------------------------------
extern "C" void kernel_launch(void* const* d_in, const int* in_sizes, int n_in,
                              void* d_out, int out_size) {
    const float* x      = (const float*)d_in[0];
    const int*   ei     = (const int*)  d_in[1];   // [2,E]: first E = src, next E = dst
    const float* gf     = (const float*)d_in[2];
    const float* w_node = (const float*)d_in[3];
    const float* b_node = (const float*)d_in[4];
    const float* w_glob = (const float*)d_in[5];
    const float* b_glob = (const float*)d_in[6];
    const float* w_c[3] = {(const float*)d_in[7], (const float*)d_in[9],  (const float*)d_in[11]};
    const float* b_c[3] = {(const float*)d_in[8], (const float*)d_in[10], (const float*)d_in[12]};
    const float* w_fc1  = (const float*)d_in[13];
    const float* b_fc1  = (const float*)d_in[14];
    const float* w_fc2  = (const float*)d_in[15];
    const float* b_fc2  = (const float*)d_in[16];
    float* out = (float*)d_out;

    __half *p_hf, *p_wh;
    unsigned int *p_hw8;
    int *p_cnt;
    cudaGetSymbolAddress((void**)&p_hf,  g_hf);
    cudaGetSymbolAddress((void**)&p_wh,  g_wh);
    cudaGetSymbolAddress((void**)&p_hw8, g_hw8);
    cudaGetSymbolAddress((void**)&p_cnt, g_cnt);

    static cudaStream_t s_side = nullptr;
    static cudaEvent_t  s_evFork = nullptr, s_evFill = nullptr;
    if (!s_side) {
        cudaStreamCreateWithFlags(&s_side, cudaStreamNonBlocking);
        cudaEventCreateWithFlags(&s_evFork, cudaEventDisableTiming);
        cudaEventCreateWithFlags(&s_evFill, cudaEventDisableTiming);
    }

    const int TB = 256;
    const int HG = (N_NODES + 127) / 128;   // 782 blocks

    // fork: CSR build on side stream (memset -> slot fill -> dis)
    cudaEventRecord(s_evFork, 0);
    cudaStreamWaitEvent(s_side, s_evFork, 0);
    cudaMemsetAsync(p_cnt, 0, N_NODES * sizeof(int), s_side);
    k_fill<<<(N_EDGES + TB - 1) / TB, TB, 0, s_side>>>(ei, ei + N_EDGES);
    k_dis <<<(N_NODES + TB - 1) / TB, TB, 0, s_side>>>();
    cudaEventRecord(s_evFill, s_side);

    // main (concurrent with CSR build): prep (Wc=Wn@W0, bc, fp16 W1/W2),
    // then layer-1 HMMA over x with combined weights (UNSCALED -> no graph dep)
    k_prep<<<9, 256>>>(w_c[0], w_c[1], w_c[2], w_node, b_node);
    k_hmma1<<<HG, 256>>>(x, p_hw8);

    // join: aggregation needs CSR + dis
    cudaStreamWaitEvent(0, s_evFill, 0);
    k_agg<true><<<(N_NODES * 32 + TB - 1) / TB, TB>>>((const uint4*)p_hw8, b_c[0], p_hf);

    for (int l = 1; l < 3; l++) {
        k_hmma<<<HG, 256>>>(p_hf, &((__half(*)[HDIM*HDIM])p_wh)[l][0], p_hw8);
        k_agg<false><<<(N_NODES * 32 + TB - 1) / TB, TB>>>((const uint4*)p_hw8, b_c[l], p_hf);
    }

    // pool + head
    k_pool<<<256, 256>>>((const __half2*)p_hf);
    k_head<<<1, 64>>>(gf, w_glob, b_glob, w_fc1, b_fc1, w_fc2, b_fc2, out);
}

// round 16
// speedup vs baseline: 1.1375x; 1.1375x over previous
#include <cuda_runtime.h>
#include <cuda_fp16.h>
#include <cuda_fp8.h>
#include <cstdint>

#define N_NODES 100000
#define N_EDGES 1600000
#define FNODE   32
#define FGLOB   16
#define HDIM    64
#define OUTDIM  64
#define MAXDEG  128    // Poisson(16) max over 100k nodes ~50; 128 is a >=8-sigma bound

#define MSG_SCALE     64.0f
#define INV_MSG_SCALE (1.0f / 64.0f)

#define HALF0 50048                      // 391 * 128, first-half node count
#define HALF1 (N_NODES - HALF0)          // 49952

// ---------------- scratch (device globals: no allocations allowed) ----------
__device__ int   g_cnt[N_NODES];                                 // degree; fill cursor
__device__ __align__(16) int g_csr[(size_t)N_NODES * MAXDEG];    // slot-based CSR
__device__ float g_dis[N_NODES];
__device__ __align__(16) __half g_wh[3][HDIM * HDIM];            // [0]=Wc(32x64), [1],[2]=fp16 W
__device__ float g_bc[HDIM];                                     // bc = bn @ W0
__device__ __align__(16) __half g_hf[(size_t)N_NODES * HDIM];    // node features fp16
__device__ __align__(16) unsigned int g_hw8a[(size_t)N_NODES * 16]; // fp8x4 msgs, 64B/row
__device__ __align__(16) unsigned int g_hw8b[(size_t)N_NODES * 16];
__device__ float g_pool[HDIM];

// ---------------- cp.async helpers ------------------------------------------------
__device__ __forceinline__ void cp16(uint32_t saddr, const void* g) {
    asm volatile("cp.async.cg.shared.global [%0], [%1], 16;\n" :: "r"(saddr), "l"(g));
}
#define CP_COMMIT() asm volatile("cp.async.commit_group;\n" ::: "memory")
#define CP_WAIT0()  asm volatile("cp.async.wait_group 0;\n" ::: "memory")

// ---------------- prep: Wc = Wn@W0, bc = bn@W0 (block 0); W1,W2 -> fp16 ----------
__global__ void k_prep(const float* __restrict__ w0, const float* __restrict__ w1,
                       const float* __restrict__ w2, const float* __restrict__ wn,
                       const float* __restrict__ bn) {
    if (blockIdx.x == 0) {
        __shared__ float WnS[FNODE * HDIM];
        __shared__ float W0S[HDIM * HDIM];
        int tid = threadIdx.x;
        for (int i = tid; i < FNODE * HDIM / 4; i += 256)
            reinterpret_cast<float4*>(WnS)[i] = reinterpret_cast<const float4*>(wn)[i];
        for (int i = tid; i < HDIM * HDIM / 4; i += 256)
            reinterpret_cast<float4*>(W0S)[i] = reinterpret_cast<const float4*>(w0)[i];
        __syncthreads();
        for (int idx = tid; idx < FNODE * HDIM; idx += 256) {
            int i = idx >> 6, j = idx & 63;
            float s = 0.f;
            #pragma unroll 8
            for (int k = 0; k < HDIM; k++) s += WnS[i * HDIM + k] * W0S[k * HDIM + j];
            g_wh[0][idx] = __float2half(s);
        }
        if (tid < HDIM) {
            float s = 0.f;
            #pragma unroll 8
            for (int k = 0; k < HDIM; k++) s += bn[k] * W0S[k * HDIM + tid];
            g_bc[tid] = s;
        }
    } else {
        int base = (blockIdx.x - 1) * blockDim.x + threadIdx.x;
        int stride = (gridDim.x - 1) * blockDim.x;
        for (int idx = base; idx < 2 * HDIM * HDIM; idx += stride) {
            if (idx < HDIM * HDIM) g_wh[1][idx] = __float2half(w1[idx]);
            else                   g_wh[2][idx - HDIM * HDIM] = __float2half(w2[idx - HDIM * HDIM]);
        }
    }
}

// ---------------- fused count+fill: slot-based CSR (one atomic per edge) ---------
__global__ void k_fill(const int* __restrict__ src, const int* __restrict__ dst) {
    int e = blockIdx.x * blockDim.x + threadIdx.x;
    if (e < N_EDGES) {
        int d = dst[e];
        int slot = atomicAdd(&g_cnt[d], 1);
        g_csr[(size_t)d * MAXDEG + slot] = src[e];
    }
}

// ---------------- dis = rsqrt(cnt+1) + pool zero ----------------------------------
__global__ void k_dis() {
    int i = blockIdx.x * blockDim.x + threadIdx.x;
    if (i < N_NODES) g_dis[i] = rsqrtf((float)(g_cnt[i] + 1));
    if (i < HDIM) g_pool[i] = 0.f;
}

// ---------------- fp8x2 -> half2 helpers -----------------------------------------
__device__ __forceinline__ __half2 fp8x2_to_h2(unsigned short u) {
    __half2_raw hr = __nv_cvt_fp8x2_to_halfraw2(u, __NV_E4M3);
    return *reinterpret_cast<__half2*>(&hr);
}
__device__ __forceinline__ __half2 u2h2(unsigned int u) {
    return *reinterpret_cast<__half2*>(&u);
}

#define APITCH 72      // halves; conflict-free ldmatrix (144B rows)
#define S8P    36      // ushorts per padded fp8 row (32 data + 4 pad)

// ---------------- layer-1 HMMA: msgs = fp8(64 * (x @ Wc + bc)), K=32 --------------
// UNSCALED by dis (applied per-edge in agg) -> no dependence on the graph build.
__global__ void k_hmma1(const float* __restrict__ xin, unsigned int* __restrict__ out8) {
    __shared__ __half Wsm[FNODE * APITCH];    // Wc: 32 K-rows x 64 cols
    __shared__ __half Asm[128 * APITCH];
    __shared__ float BcS[HDIM];
    int tid = threadIdx.x;
    int lane = tid & 31, wid = tid >> 5;
    int rowBase = blockIdx.x * 128;

    for (int i = tid; i < FNODE * 8; i += 256) {
        int r = i >> 3, c8 = i & 7;
        *reinterpret_cast<uint4*>(&Wsm[r * APITCH + c8 * 8]) =
            *reinterpret_cast<const uint4*>(&g_wh[0][r * HDIM + c8 * 8]);
    }
    if (tid < HDIM) BcS[tid] = g_bc[tid];

    for (int i = tid; i < 128 * 4; i += 256) {
        int r = i >> 2, c8 = i & 3;
        int gr = rowBase + r;
        uint4 hv = make_uint4(0u, 0u, 0u, 0u);
        if (gr < N_NODES) {
            const float4* xr = reinterpret_cast<const float4*>(xin + (size_t)gr * FNODE + c8 * 8);
            float4 a = __ldg(&xr[0]);
            float4 b = __ldg(&xr[1]);
            __half2 h0 = __floats2half2_rn(a.x, a.y);
            __half2 h1 = __floats2half2_rn(a.z, a.w);
            __half2 h2 = __floats2half2_rn(b.x, b.y);
            __half2 h3 = __floats2half2_rn(b.z, b.w);
            hv.x = *reinterpret_cast<unsigned*>(&h0);
            hv.y = *reinterpret_cast<unsigned*>(&h1);
            hv.z = *reinterpret_cast<unsigned*>(&h2);
            hv.w = *reinterpret_cast<unsigned*>(&h3);
        }
        *reinterpret_cast<uint4*>(&Asm[r * APITCH + c8 * 8]) = hv;
    }
    __syncthreads();

    float acc[8][4];
    #pragma unroll
    for (int j = 0; j < 8; j++)
        #pragma unroll
        for (int q = 0; q < 4; q++) acc[j][q] = 0.f;

    uint32_t aAddr = (uint32_t)__cvta_generic_to_shared(
        &Asm[(wid * 16 + (lane & 15)) * APITCH + (lane >> 4) * 8]);
    uint32_t bAddr = (uint32_t)__cvta_generic_to_shared(
        &Wsm[(lane & 15) * APITCH]);

    #pragma unroll
    for (int k = 0; k < 2; k++) {             // K=32 -> 2 k-steps
        uint32_t a0, a1, a2, a3;
        asm volatile("ldmatrix.sync.aligned.m8n8.x4.shared.b16 {%0,%1,%2,%3}, [%4];\n"
                     : "=r"(a0), "=r"(a1), "=r"(a2), "=r"(a3)
                     : "r"(aAddr + k * 16 * 2));
        #pragma unroll
        for (int j = 0; j < 8; j++) {
            uint32_t b0, b1;
            asm volatile("ldmatrix.sync.aligned.m8n8.x2.trans.shared.b16 {%0,%1}, [%2];\n"
                         : "=r"(b0), "=r"(b1)
                         : "r"(bAddr + (k * 16 * APITCH + j * 8) * 2));
            asm volatile("mma.sync.aligned.m16n8k16.row.col.f32.f16.f16.f32 "
                         "{%0,%1,%2,%3}, {%4,%5,%6,%7}, {%8,%9}, {%0,%1,%2,%3};\n"
                         : "+f"(acc[j][0]), "+f"(acc[j][1]), "+f"(acc[j][2]), "+f"(acc[j][3])
                         : "r"(a0), "r"(a1), "r"(a2), "r"(a3), "r"(b0), "r"(b1));
        }
    }

    __syncthreads();
    unsigned short* S8 = reinterpret_cast<unsigned short*>(Asm);   // [128][S8P]

    int g = lane >> 2, q = lane & 3;
    int r0l = wid * 16 + g;
    int r1l = r0l + 8;
    #pragma unroll
    for (int j = 0; j < 8; j++) {
        float bcx = BcS[j * 8 + q * 2];
        float bcy = BcS[j * 8 + q * 2 + 1];
        S8[r0l * S8P + j * 4 + q] = __nv_cvt_float2_to_fp8x2(
            make_float2((acc[j][0] + bcx) * MSG_SCALE, (acc[j][1] + bcy) * MSG_SCALE),
            __NV_SATFINITE, __NV_E4M3);
        S8[r1l * S8P + j * 4 + q] = __nv_cvt_float2_to_fp8x2(
            make_float2((acc[j][2] + bcx) * MSG_SCALE, (acc[j][3] + bcy) * MSG_SCALE),
            __NV_SATFINITE, __NV_E4M3);
    }
    __syncthreads();

    for (int i = tid; i < 128 * 8; i += 256) {
        int r = i >> 3, c = i & 7;
        int grow = rowBase + r;
        if (grow < N_NODES) {
            uint2 v = *reinterpret_cast<const uint2*>(&S8[r * S8P + c * 4]);
            *reinterpret_cast<uint2*>(&out8[(size_t)grow * 16 + c * 2]) = v;
        }
    }
}

// ---------------- HMMA conv transform (layers 2,3): pre-scaled msgs ---------------
// rowBeg: node-row offset (half-split pipelining). cp.async staging for W and A.
__global__ void k_hmma(const __half* __restrict__ hin, const __half* __restrict__ wh,
                       unsigned int* __restrict__ out8, int rowBeg) {
    __shared__ __half Wsm[HDIM * APITCH];
    __shared__ __half Asm[128 * APITCH];
    int tid = threadIdx.x;
    int lane = tid & 31, wid = tid >> 5;
    int rowBase = rowBeg + blockIdx.x * 128;

    uint32_t wBase = (uint32_t)__cvta_generic_to_shared(Wsm);
    uint32_t aBase = (uint32_t)__cvta_generic_to_shared(Asm);

    for (int i = tid; i < HDIM * 8; i += 256) {
        int r = i >> 3, c8 = i & 7;
        cp16(wBase + (uint32_t)(r * APITCH + c8 * 8) * 2, wh + r * HDIM + c8 * 8);
    }
    for (int i = tid; i < 128 * 8; i += 256) {
        int r = i >> 3, c8 = i & 7;
        int gr = rowBase + r;
        if (gr < N_NODES)
            cp16(aBase + (uint32_t)(r * APITCH + c8 * 8) * 2, hin + (size_t)gr * HDIM + c8 * 8);
        else
            *reinterpret_cast<uint4*>(&Asm[r * APITCH + c8 * 8]) = make_uint4(0u, 0u, 0u, 0u);
    }
    CP_COMMIT();
    CP_WAIT0();
    __syncthreads();

    float acc[8][4];
    #pragma unroll
    for (int j = 0; j < 8; j++)
        #pragma unroll
        for (int q = 0; q < 4; q++) acc[j][q] = 0.f;

    uint32_t aAddr = (uint32_t)__cvta_generic_to_shared(
        &Asm[(wid * 16 + (lane & 15)) * APITCH + (lane >> 4) * 8]);
    uint32_t bAddr = (uint32_t)__cvta_generic_to_shared(
        &Wsm[(lane & 15) * APITCH]);

    #pragma unroll
    for (int k = 0; k < 4; k++) {
        uint32_t a0, a1, a2, a3;
        asm volatile("ldmatrix.sync.aligned.m8n8.x4.shared.b16 {%0,%1,%2,%3}, [%4];\n"
                     : "=r"(a0), "=r"(a1), "=r"(a2), "=r"(a3)
                     : "r"(aAddr + k * 16 * 2));
        #pragma unroll
        for (int j = 0; j < 8; j++) {
            uint32_t b0, b1;
            asm volatile("ldmatrix.sync.aligned.m8n8.x2.trans.shared.b16 {%0,%1}, [%2];\n"
                         : "=r"(b0), "=r"(b1)
                         : "r"(bAddr + (k * 16 * APITCH + j * 8) * 2));
            asm volatile("mma.sync.aligned.m16n8k16.row.col.f32.f16.f16.f32 "
                         "{%0,%1,%2,%3}, {%4,%5,%6,%7}, {%8,%9}, {%0,%1,%2,%3};\n"
                         : "+f"(acc[j][0]), "+f"(acc[j][1]), "+f"(acc[j][2]), "+f"(acc[j][3])
                         : "r"(a0), "r"(a1), "r"(a2), "r"(a3), "r"(b0), "r"(b1));
        }
    }

    __syncthreads();
    unsigned short* S8 = reinterpret_cast<unsigned short*>(Asm);   // [128][S8P]

    int g = lane >> 2, q = lane & 3;
    int r0l = wid * 16 + g;
    int r1l = r0l + 8;
    int gr0 = rowBase + r0l, gr1 = rowBase + r1l;
    float d0 = (gr0 < N_NODES) ? g_dis[gr0] * MSG_SCALE : 0.f;
    float d1 = (gr1 < N_NODES) ? g_dis[gr1] * MSG_SCALE : 0.f;
    #pragma unroll
    for (int j = 0; j < 8; j++) {
        S8[r0l * S8P + j * 4 + q] = __nv_cvt_float2_to_fp8x2(
            make_float2(acc[j][0] * d0, acc[j][1] * d0), __NV_SATFINITE, __NV_E4M3);
        S8[r1l * S8P + j * 4 + q] = __nv_cvt_float2_to_fp8x2(
            make_float2(acc[j][2] * d1, acc[j][3] * d1), __NV_SATFINITE, __NV_E4M3);
    }
    __syncthreads();

    for (int i = tid; i < 128 * 8; i += 256) {
        int r = i >> 3, c = i & 7;
        int grow = rowBase + r;
        if (grow < N_NODES) {
            uint2 v = *reinterpret_cast<const uint2*>(&S8[r * S8P + c * 4]);
            *reinterpret_cast<uint2*>(&out8[(size_t)grow * 16 + c * 2]) = v;
        }
    }
}

// ---------------- aggregation (r14 champion geometry): 8 lanes/row, 4 edges/LDG --
// EDIS=true : msgs unscaled -> per-edge dis[src] applied via hfma2 (layer 1)
// EDIS=false: msgs pre-scaled by dis[src] (layers 2,3)
// nodeBeg/nodeEnd: half-split range.
template<bool EDIS>
__global__ void k_agg(const uint2* __restrict__ hw,
                      const float* __restrict__ bias, __half* __restrict__ outh,
                      int nodeBeg, int nodeEnd) {
    int gw = nodeBeg + ((blockIdx.x * blockDim.x + threadIdx.x) >> 5);
    int lane = threadIdx.x & 31;
    if (gw >= nodeEnd) return;
    int e = lane >> 3;           // edge slot 0..3
    int s = lane & 7;            // uint2 column (8 fp8 cols)

    float disg = __ldg(&g_dis[gw]);

    __half2 acc0 = __float2half2_rn(0.f), acc1 = acc0, acc2 = acc0, acc3 = acc0;

    if (e == 0) {                // self loop
        uint2 v = __ldg(&hw[(size_t)gw * 8 + s]);
        __half2 v0 = fp8x2_to_h2((unsigned short)(v.x & 0xffffu));
        __half2 v1 = fp8x2_to_h2((unsigned short)(v.x >> 16));
        __half2 v2 = fp8x2_to_h2((unsigned short)(v.y & 0xffffu));
        __half2 v3 = fp8x2_to_h2((unsigned short)(v.y >> 16));
        if (EDIS) {
            __half2 dh = __float2half2_rn(disg);
            acc0 = __hmul2(v0, dh); acc1 = __hmul2(v1, dh);
            acc2 = __hmul2(v2, dh); acc3 = __hmul2(v3, dh);
        } else {
            acc0 = v0; acc1 = v1; acc2 = v2; acc3 = v3;
        }
    }

    int cnt = g_cnt[gw];
    const int* row = g_csr + (size_t)gw * MAXDEG;
    int j = 0;
    for (; j + 4 <= cnt; j += 4) {
        int idx = __ldg(&row[j + e]);
        uint2 v = __ldg(&hw[(size_t)idx * 8 + s]);
        __half2 v0 = fp8x2_to_h2((unsigned short)(v.x & 0xffffu));
        __half2 v1 = fp8x2_to_h2((unsigned short)(v.x >> 16));
        __half2 v2 = fp8x2_to_h2((unsigned short)(v.y & 0xffffu));
        __half2 v3 = fp8x2_to_h2((unsigned short)(v.y >> 16));
        if (EDIS) {
            __half2 dh = __float2half2_rn(__ldg(&g_dis[idx]));
            acc0 = __hfma2(v0, dh, acc0); acc1 = __hfma2(v1, dh, acc1);
            acc2 = __hfma2(v2, dh, acc2); acc3 = __hfma2(v3, dh, acc3);
        } else {
            acc0 = __hadd2(acc0, v0); acc1 = __hadd2(acc1, v1);
            acc2 = __hadd2(acc2, v2); acc3 = __hadd2(acc3, v3);
        }
    }
    int rem = cnt - j;           // 0..3, warp-uniform
    if (e < rem) {
        int idx = __ldg(&row[j + e]);
        uint2 v = __ldg(&hw[(size_t)idx * 8 + s]);
        __half2 v0 = fp8x2_to_h2((unsigned short)(v.x & 0xffffu));
        __half2 v1 = fp8x2_to_h2((unsigned short)(v.x >> 16));
        __half2 v2 = fp8x2_to_h2((unsigned short)(v.y & 0xffffu));
        __half2 v3 = fp8x2_to_h2((unsigned short)(v.y >> 16));
        if (EDIS) {
            __half2 dh = __float2half2_rn(__ldg(&g_dis[idx]));
            acc0 = __hfma2(v0, dh, acc0); acc1 = __hfma2(v1, dh, acc1);
            acc2 = __hfma2(v2, dh, acc2); acc3 = __hfma2(v3, dh, acc3);
        } else {
            acc0 = __hadd2(acc0, v0); acc1 = __hadd2(acc1, v1);
            acc2 = __hadd2(acc2, v2); acc3 = __hadd2(acc3, v3);
        }
    }

    // reduce across edge slots (xor 8, then 16)
    unsigned ua0 = *reinterpret_cast<unsigned*>(&acc0);
    unsigned ua1 = *reinterpret_cast<unsigned*>(&acc1);
    unsigned ua2 = *reinterpret_cast<unsigned*>(&acc2);
    unsigned ua3 = *reinterpret_cast<unsigned*>(&acc3);
    acc0 = __hadd2(u2h2(ua0), u2h2(__shfl_xor_sync(0xffffffffu, ua0, 8)));
    acc1 = __hadd2(u2h2(ua1), u2h2(__shfl_xor_sync(0xffffffffu, ua1, 8)));
    acc2 = __hadd2(u2h2(ua2), u2h2(__shfl_xor_sync(0xffffffffu, ua2, 8)));
    acc3 = __hadd2(u2h2(ua3), u2h2(__shfl_xor_sync(0xffffffffu, ua3, 8)));
    ua0 = *reinterpret_cast<unsigned*>(&acc0);
    ua1 = *reinterpret_cast<unsigned*>(&acc1);
    ua2 = *reinterpret_cast<unsigned*>(&acc2);
    ua3 = *reinterpret_cast<unsigned*>(&acc3);
    acc0 = __hadd2(u2h2(ua0), u2h2(__shfl_xor_sync(0xffffffffu, ua0, 16)));
    acc1 = __hadd2(u2h2(ua1), u2h2(__shfl_xor_sync(0xffffffffu, ua1, 16)));
    acc2 = __hadd2(u2h2(ua2), u2h2(__shfl_xor_sync(0xffffffffu, ua2, 16)));
    acc3 = __hadd2(u2h2(ua3), u2h2(__shfl_xor_sync(0xffffffffu, ua3, 16)));

    if (e == 0) {
        float di = disg * INV_MSG_SCALE;
        float4 bA = __ldg(reinterpret_cast<const float4*>(bias) + 2 * s);
        float4 bB = __ldg(reinterpret_cast<const float4*>(bias) + 2 * s + 1);
        float2 f0 = __half22float2(acc0), f1 = __half22float2(acc1);
        float2 f2 = __half22float2(acc2), f3 = __half22float2(acc3);
        __half2 h0 = __floats2half2_rn(fmaxf(fmaf(di, f0.x, bA.x), 0.f),
                                       fmaxf(fmaf(di, f0.y, bA.y), 0.f));
        __half2 h1 = __floats2half2_rn(fmaxf(fmaf(di, f1.x, bA.z), 0.f),
                                       fmaxf(fmaf(di, f1.y, bA.w), 0.f));
        __half2 h2 = __floats2half2_rn(fmaxf(fmaf(di, f2.x, bB.x), 0.f),
                                       fmaxf(fmaf(di, f2.y, bB.y), 0.f));
        __half2 h3 = __floats2half2_rn(fmaxf(fmaf(di, f3.x, bB.z), 0.f),
                                       fmaxf(fmaf(di, f3.y, bB.w), 0.f));
        uint4 st;
        st.x = *reinterpret_cast<unsigned*>(&h0);
        st.y = *reinterpret_cast<unsigned*>(&h1);
        st.z = *reinterpret_cast<unsigned*>(&h2);
        st.w = *reinterpret_cast<unsigned*>(&h3);
        *reinterpret_cast<uint4*>(outh + (size_t)gw * HDIM + s * 8) = st;
    }
}

// ---------------- mean pool over a node range (fp16 input) ------------------------
__global__ void k_pool(const __half2* __restrict__ h2, int rowBeg, int rowCnt) {
    __shared__ float2 sh[256];
    int c = threadIdx.x & 31;       // half2 column
    int seg = threadIdx.x >> 5;     // 0..7
    float2 acc = make_float2(0.f, 0.f);
    for (int r = blockIdx.x * 8 + seg; r < rowCnt; r += gridDim.x * 8) {
        float2 v = __half22float2(h2[(size_t)(rowBeg + r) * 32 + c]);
        acc.x += v.x; acc.y += v.y;
    }
    sh[threadIdx.x] = acc;
    __syncthreads();
    if (threadIdx.x < 32) {
        float2 s = sh[c];
        #pragma unroll
        for (int k = 1; k < 8; k++) {
            s.x += sh[k * 32 + c].x;
            s.y += sh[k * 32 + c].y;
        }
        atomicAdd(&g_pool[2 * c],     s.x);
        atomicAdd(&g_pool[2 * c + 1], s.y);
    }
}

// ---------------- head ------------------------------------------------------------
__global__ void k_head(const float* __restrict__ gf,
                       const float* __restrict__ w_glob, const float* __restrict__ b_glob,
                       const float* __restrict__ w_fc1, const float* __restrict__ b_fc1,
                       const float* __restrict__ w_fc2, const float* __restrict__ b_fc2,
                       float* __restrict__ out) {
    __shared__ float xc[2 * HDIM];
    __shared__ float t1[HDIM];
    int t = threadIdx.x;

    xc[t] = g_pool[t] * (1.0f / (float)N_NODES);

    float a = b_glob[t];
    #pragma unroll
    for (int k = 0; k < FGLOB; k++) a += gf[k] * w_glob[k * HDIM + t];
    xc[HDIM + t] = fmaxf(a, 0.f);
    __syncthreads();

    float u = b_fc1[t];
    #pragma unroll 8
    for (int k = 0; k < 2 * HDIM; k++) u += xc[k] * w_fc1[k * HDIM + t];
    t1[t] = fmaxf(u, 0.f);
    __syncthreads();

    float o = b_fc2[t];
    #pragma unroll 8
    for (int k = 0; k < HDIM; k++) o += t1[k] * w_fc2[k * OUTDIM + t];
    out[t] = o;
}

// ---------------- launch ------------------------------------------------------
extern "C" void kernel_launch(void* const* d_in, const int* in_sizes, int n_in,
                              void* d_out, int out_size) {
    const float* x      = (const float*)d_in[0];
    const int*   ei     = (const int*)  d_in[1];   // [2,E]: first E = src, next E = dst
    const float* gf     = (const float*)d_in[2];
    const float* w_node = (const float*)d_in[3];
    const float* b_node = (const float*)d_in[4];
    const float* w_glob = (const float*)d_in[5];
    const float* b_glob = (const float*)d_in[6];
    const float* w_c[3] = {(const float*)d_in[7], (const float*)d_in[9],  (const float*)d_in[11]};
    const float* b_c[3] = {(const float*)d_in[8], (const float*)d_in[10], (const float*)d_in[12]};
    const float* w_fc1  = (const float*)d_in[13];
    const float* b_fc1  = (const float*)d_in[14];
    const float* w_fc2  = (const float*)d_in[15];
    const float* b_fc2  = (const float*)d_in[16];
    float* out = (float*)d_out;

    __half *p_hf, *p_wh;
    unsigned int *p_a, *p_b;
    int *p_cnt;
    cudaGetSymbolAddress((void**)&p_hf,  g_hf);
    cudaGetSymbolAddress((void**)&p_wh,  g_wh);
    cudaGetSymbolAddress((void**)&p_a,   g_hw8a);
    cudaGetSymbolAddress((void**)&p_b,   g_hw8b);
    cudaGetSymbolAddress((void**)&p_cnt, g_cnt);
    __half* p_w1 = &((__half(*)[HDIM * HDIM])p_wh)[1][0];
    __half* p_w2 = &((__half(*)[HDIM * HDIM])p_wh)[2][0];

    static cudaStream_t s_side = nullptr;
    static cudaEvent_t  evFork = nullptr, evFill = nullptr, evH1 = nullptr;
    static cudaEvent_t  evM[2] = {nullptr, nullptr};
    static cudaEvent_t  evS[3] = {nullptr, nullptr, nullptr};
    if (!s_side) {
        cudaStreamCreateWithFlags(&s_side, cudaStreamNonBlocking);
        cudaEventCreateWithFlags(&evFork, cudaEventDisableTiming);
        cudaEventCreateWithFlags(&evFill, cudaEventDisableTiming);
        cudaEventCreateWithFlags(&evH1,   cudaEventDisableTiming);
        for (int i = 0; i < 2; i++) cudaEventCreateWithFlags(&evM[i], cudaEventDisableTiming);
        for (int i = 0; i < 3; i++) cudaEventCreateWithFlags(&evS[i], cudaEventDisableTiming);
    }

    const int TB = 256;
    const int AG0 = (HALF0 * 32 + TB - 1) / TB;   // agg blocks, first half
    const int AG1 = (HALF1 * 32 + TB - 1) / TB;   // agg blocks, second half
    const int HG0 = HALF0 / 128;                  // 391
    const int HG1 = (HALF1 + 127) / 128;          // 391

    // fork: CSR build on side stream (memset -> slot fill -> dis)
    cudaEventRecord(evFork, 0);
    cudaStreamWaitEvent(s_side, evFork, 0);
    cudaMemsetAsync(p_cnt, 0, N_NODES * sizeof(int), s_side);
    k_fill<<<(N_EDGES + TB - 1) / TB, TB, 0, s_side>>>(ei, ei + N_EDGES);
    k_dis <<<(N_NODES + TB - 1) / TB, TB, 0, s_side>>>();
    cudaEventRecord(evFill, s_side);

    // main (concurrent with CSR build): prep + layer-1 HMMA (unscaled -> bufA)
    k_prep<<<9, 256>>>(w_c[0], w_c[1], w_c[2], w_node, b_node);
    k_hmma1<<<(N_NODES + 127) / 128, 256>>>(x, p_a);
    cudaEventRecord(evH1, 0);

    // joins for layer-1 aggregation
    cudaStreamWaitEvent(0, evFill, 0);        // main needs CSR+dis
    cudaStreamWaitEvent(s_side, evH1, 0);     // side needs bufA msgs

    // ---- layer 1 agg + layer 2 transform, half-split across streams ----
    k_agg<true><<<AG0, TB>>>((const uint2*)p_a, b_c[0], p_hf, 0, HALF0);
    k_hmma<<<HG0, 256>>>(p_hf, p_w1, p_b, 0);
    cudaEventRecord(evM[0], 0);
    k_agg<true><<<AG1, TB, 0, s_side>>>((const uint2*)p_a, b_c[0], p_hf, HALF0, N_NODES);
    k_hmma<<<HG1, 256, 0, s_side>>>(p_hf, p_w1, p_b, HALF0);
    cudaEventRecord(evS[0], s_side);

    // ---- layer 2 agg + layer 3 transform ----
    cudaStreamWaitEvent(0, evS[0], 0);        // agg2 reads all of bufB
    k_agg<false><<<AG0, TB>>>((const uint2*)p_b, b_c[1], p_hf, 0, HALF0);
    k_hmma<<<HG0, 256>>>(p_hf, p_w2, p_a, 0);
    cudaEventRecord(evM[1], 0);
    cudaStreamWaitEvent(s_side, evM[0], 0);
    k_agg<false><<<AG1, TB, 0, s_side>>>((const uint2*)p_b, b_c[1], p_hf, HALF0, N_NODES);
    k_hmma<<<HG1, 256, 0, s_side>>>(p_hf, p_w2, p_a, HALF0);
    cudaEventRecord(evS[1], s_side);

    // ---- layer 3 agg + pool ----
    cudaStreamWaitEvent(0, evS[1], 0);        // agg3 reads all of bufA
    k_agg<false><<<AG0, TB>>>((const uint2*)p_a, b_c[2], p_hf, 0, HALF0);
    k_pool<<<128, 256>>>((const __half2*)p_hf, 0, HALF0);
    cudaStreamWaitEvent(s_side, evM[1], 0);
    k_agg<false><<<AG1, TB, 0, s_side>>>((const uint2*)p_a, b_c[2], p_hf, HALF0, N_NODES);
    k_pool<<<128, 256, 0, s_side>>>((const __half2*)p_hf, HALF0, HALF1);
    cudaEventRecord(evS[2], s_side);

    // head
    cudaStreamWaitEvent(0, evS[2], 0);
    k_head<<<1, 64>>>(gf, w_glob, b_glob, w_fc1, b_fc1, w_fc2, b_fc2, out);
}